// round 16
// baseline (speedup 1.0000x reference)
#include <cuda_runtime.h>
#include <cuda_bf16.h>
#include <cstdint>
#include <math.h>

#define VOCABSZ 32000
#define VPAD    32128
#define WORDVEC 256
#define HIDDEN  512
#define TSTEPS  256
#define NBATCH  16
#define G4      2048
#define MROWS   4096
#define NTILN   251          // VPAD / 128
#define NJOBS   (32 * NTILN) // 8032
#define VCTAS   148
#define LCTAS   64
#define LOG2E   1.44269504f

// ---------------- device scratch ----------------
__device__ float          g_xw[TSTEPS * NBATCH * G4];
__device__ __nv_bfloat16  g_hb[MROWS * HIDDEN];            // bf16 h history (written by lstm)
__device__ __nv_bfloat16  g_wvb[(size_t)VPAD * HIDDEN];    // Wv^T bf16 [v][k]
__device__ __nv_bfloat16  g_xb[MROWS * WORDVEC];           // gathered embeddings bf16
__device__ __nv_bfloat16  g_wxT[G4 * WORDVEC];             // Wx^T bf16
__device__ float          g_bv2[VPAD];                     // bv * LOG2E (pad = -120)
__device__ uint32_t       g_hpk2[2][NBATCH * HIDDEN];      // packed (hi,lo) bf16 h state
__device__ unsigned       g_barc[TSTEPS];
__device__ float          g_ps_flat[MROWS];                // per-row exp-sums (atomic)
__device__ float          g_lt[MROWS];

// ---------------- helpers ----------------
__device__ __forceinline__ float sigf(float x) { return __fdividef(1.f, 1.f + __expf(-x)); }
__device__ __forceinline__ float tanhf_fast(float x) { return __fdividef(2.f, 1.f + __expf(-2.f * x)) - 1.f; }
__device__ __forceinline__ uint32_t smem_to_u32(const void* p) {
    uint32_t a;
    asm("{ .reg .u64 t; cvta.to.shared.u64 t, %1; cvt.u32.u64 %0, t; }" : "=r"(a) : "l"(p));
    return a;
}
__device__ __forceinline__ float bf16lo_f(uint32_t u) { return __uint_as_float(u << 16); }
__device__ __forceinline__ float bf16hi_f(uint32_t u) { return __uint_as_float(u & 0xffff0000u); }
#define LDSM_X4(r, addr) asm volatile( \
    "ldmatrix.sync.aligned.m8n8.x4.shared.b16 {%0,%1,%2,%3}, [%4];" \
    : "=r"((r)[0]), "=r"((r)[1]), "=r"((r)[2]), "=r"((r)[3]) : "r"(addr))
#define LDSM_X2(r, addr) asm volatile( \
    "ldmatrix.sync.aligned.m8n8.x2.shared.b16 {%0,%1}, [%2];" \
    : "=r"((r)[0]), "=r"((r)[1]) : "r"(addr))
#define MMA16816(d, a, b0, b1) asm volatile( \
    "mma.sync.aligned.m16n8k16.row.col.f32.bf16.bf16.f32 " \
    "{%0,%1,%2,%3}, {%4,%5,%6,%7}, {%8,%9}, {%0,%1,%2,%3};" \
    : "+f"((d)[0]), "+f"((d)[1]), "+f"((d)[2]), "+f"((d)[3]) \
    : "r"((a)[0]), "r"((a)[1]), "r"((a)[2]), "r"((a)[3]), "r"(b0), "r"(b1))

__device__ __forceinline__ float exp2_fast(float t) {
    int i = __float2int_rn(t);
    float f = t - (float)i;
    float p = fmaf(f, 0.00133335581f, 0.00961812911f);
    p = fmaf(f, p, 0.0555041087f);
    p = fmaf(f, p, 0.240226507f);
    p = fmaf(f, p, 0.693147181f);
    p = fmaf(f, p, 1.0f);
    return __int_as_float(__float_as_int(p) + (i << 23));
}

__device__ __forceinline__ void grid_barrier(int idx, unsigned nblocks) {
    __threadfence();
    __syncthreads();
    if (threadIdx.x == 0) {
        atomicAdd(&g_barc[idx], 1u);
        volatile unsigned* p = &g_barc[idx];
        while (*p < nblocks) { }
        __threadfence();
    }
    __syncthreads();
}

// ---------------- init (every replay) ----------------
__global__ void __launch_bounds__(256) init_kernel(
    const float* __restrict__ h_init, const float* __restrict__ bv)
{
    int gid = blockIdx.x * 256 + threadIdx.x;            // 8192 threads
    if (gid < TSTEPS) g_barc[gid] = 0u;
    if (gid < MROWS) g_ps_flat[gid] = 0.f;
    if (gid < NBATCH * HIDDEN) {
        int k = gid & 511;
        float v = h_init[k];
        __nv_bfloat16 hi = __float2bfloat16(v);
        float hif = __bfloat162float(hi);
        __nv_bfloat16 lo = __float2bfloat16(v - hif);
        g_hpk2[0][gid] = ((uint32_t)*(uint16_t*)&hi << 16) | *(uint16_t*)&lo;
    }
    for (int j = gid; j < (VPAD - VOCABSZ) * HIDDEN; j += 8192)
        g_wvb[(size_t)VOCABSZ * HIDDEN + j] = __float2bfloat16(0.f);
    for (int j = gid; j < VPAD; j += 8192)
        g_bv2[j] = (j < VOCABSZ) ? bv[j] * LOG2E : -120.f;
}

// ---------------- prep: gather embeddings + Wx transpose (fused) ----------------
__global__ void __launch_bounds__(256) prep_kernel(
    const int* __restrict__ captions, const float* __restrict__ W_embed,
    const float* __restrict__ Wx)
{
    __shared__ float sh[32 * 33];
    if (blockIdx.x < 256) {
        int gid = blockIdx.x * 256 + threadIdx.x;
        int idx = gid * 4;
        int r = idx >> 8, d = idx & 255;
        int tok = captions[(r & 15) * 257 + (r >> 4)];
        float4 v = *(const float4*)&W_embed[tok * WORDVEC + d];
        __nv_bfloat16 o[4];
        o[0] = __float2bfloat16(v.x); o[1] = __float2bfloat16(v.y);
        o[2] = __float2bfloat16(v.z); o[3] = __float2bfloat16(v.w);
        *(uint2*)&g_xb[idx] = *(const uint2*)o;
    } else {
        int bid2 = blockIdx.x - 256;
        int n0 = (bid2 & 63) * 32, k0 = (bid2 >> 6) * 32;
        int tx = threadIdx.x & 31, ty = threadIdx.x >> 5;
        #pragma unroll
        for (int i = 0; i < 4; ++i) {
            int k = ty + i * 8;
            sh[k * 33 + tx] = Wx[(k0 + k) * G4 + n0 + tx];
        }
        __syncthreads();
        #pragma unroll
        for (int i = 0; i < 4; ++i) {
            int n = ty + i * 8;
            g_wxT[(n0 + n) * WORDVEC + k0 + tx] = __float2bfloat16(sh[tx * 33 + n]);
        }
    }
}

// ---------------- Wv transpose + bf16 ----------------
__global__ void __launch_bounds__(256) conv_wv_kernel(const float* __restrict__ Wv) {
    __shared__ float sh[32 * 33];
    int n0 = blockIdx.x * 32, k0 = blockIdx.y * 32;
    int tx = threadIdx.x & 31, ty = threadIdx.x >> 5;
    #pragma unroll
    for (int i = 0; i < 4; ++i) {
        int k = ty + i * 8;
        sh[k * 33 + tx] = Wv[(size_t)(k0 + k) * VOCABSZ + n0 + tx];
    }
    __syncthreads();
    #pragma unroll
    for (int i = 0; i < 4; ++i) {
        int n = ty + i * 8;
        g_wvb[(size_t)(n0 + n) * HIDDEN + k0 + tx] = __float2bfloat16(sh[tx * 33 + n]);
    }
}

// ---------------- embed GEMM (bf16 mma.sync) ----------------
#define E_A_STRIDE 264
#define E_B_OFF    67584
#define E_SMEM     135168
extern __shared__ __align__(16) char dsm_e[];
__global__ void __launch_bounds__(256, 1) embed_mma_kernel(const float* __restrict__ b) {
    __nv_bfloat16* As = (__nv_bfloat16*)dsm_e;
    __nv_bfloat16* Bs = (__nv_bfloat16*)(dsm_e + E_B_OFF);
    const int tid = threadIdx.x, lane = tid & 31, wid = tid >> 5;
    const int wm = wid >> 1, wn = wid & 1;
    const int mblk = blockIdx.x >> 4, nblk = blockIdx.x & 15;

    const uint4* asrc = (const uint4*)(g_xb + mblk * 128 * WORDVEC);
    const uint4* bsrc = (const uint4*)(g_wxT + nblk * 128 * WORDVEC);
    #pragma unroll
    for (int q = 0; q < 16; ++q) {
        int i = q * 256 + tid;
        int r = i >> 5, u = i & 31;
        *(uint4*)(As + r * E_A_STRIDE + u * 8) = asrc[i];
        *(uint4*)(Bs + r * E_A_STRIDE + u * 8) = bsrc[i];
    }
    __syncthreads();

    const uint32_t a_base = smem_to_u32(As);
    const uint32_t a_lane = (uint32_t)((lane & 15) * E_A_STRIDE + (lane >> 4) * 8) * 2;
    const int bq = lane >> 3;
    const uint32_t b_lane = (uint32_t)(((bq >> 1) * 8 + (lane & 7)) * E_A_STRIDE + (bq & 1) * 8) * 2;
    const uint32_t b_base = smem_to_u32(Bs) + (uint32_t)(wn * 64 * E_A_STRIDE) * 2;

    float d[2][8][4];
    #pragma unroll
    for (int mt = 0; mt < 2; ++mt)
        #pragma unroll
        for (int nt = 0; nt < 8; ++nt)
            #pragma unroll
            for (int e = 0; e < 4; ++e) d[mt][nt][e] = 0.f;

    #pragma unroll
    for (int k16 = 0; k16 < 16; ++k16) {
        const uint32_t koff = (uint32_t)(k16 * 16) * 2;
        uint32_t a[2][4];
        #pragma unroll
        for (int mt = 0; mt < 2; ++mt) {
            LDSM_X4(a[mt], a_base + a_lane + (uint32_t)((wm * 32 + mt * 16) * E_A_STRIDE) * 2 + koff);
        }
        #pragma unroll
        for (int np = 0; np < 4; ++np) {
            uint32_t bb[4];
            LDSM_X4(bb, b_base + b_lane + (uint32_t)(np * 16 * E_A_STRIDE) * 2 + koff);
            MMA16816(d[0][np * 2 + 0], a[0], bb[0], bb[1]);
            MMA16816(d[0][np * 2 + 1], a[0], bb[2], bb[3]);
            MMA16816(d[1][np * 2 + 0], a[1], bb[0], bb[1]);
            MMA16816(d[1][np * 2 + 1], a[1], bb[2], bb[3]);
        }
    }

    const int cbase = nblk * 128 + wn * 64 + (lane & 3) * 2;
    #pragma unroll
    for (int mt = 0; mt < 2; ++mt)
        #pragma unroll
        for (int rh = 0; rh < 2; ++rh) {
            int row = mblk * 128 + wm * 32 + mt * 16 + rh * 8 + (lane >> 2);
            #pragma unroll
            for (int nt = 0; nt < 8; ++nt) {
                int c = cbase + nt * 8;
                float2 v;
                v.x = d[mt][nt][rh * 2 + 0] + b[c];
                v.y = d[mt][nt][rh * 2 + 1] + b[c + 1];
                *(float2*)&g_xw[(size_t)row * G4 + c] = v;
            }
        }
}

// ---------------- persistent LSTM v4: 64 blocks, warp = (n8 rows) x (K-half) ----------
// Block owns 8 hidden units (32 gate-cols: row r = g*8+q, jcol = g*512 + bid*8 + q).
// 8 warps: rows (w&3)*8..+7, K-half (w>>2)*256. a_sh[2][32][17] partials, gates sum.
#define L_BH   0
#define L_BL   33280
#define L_AH   66560
#define L_AL   83200
#define L_ASH  99840
#define L_CSH  104192
#define L_SMEM 104704
extern __shared__ __align__(16) char dsm_l[];
__global__ void __launch_bounds__(256, 1) lstm_kernel(const float* __restrict__ Wh) {
    const int bid = blockIdx.x, tid = threadIdx.x;
    const int lane = tid & 31, wid = tid >> 5;
    uint16_t* Bh = (uint16_t*)(dsm_l + L_BH);    // [32][520]
    uint16_t* Bl = (uint16_t*)(dsm_l + L_BL);
    uint16_t* Ah = (uint16_t*)(dsm_l + L_AH);    // [16][520]
    uint16_t* Al = (uint16_t*)(dsm_l + L_AL);
    float* a_sh = (float*)(dsm_l + L_ASH);       // [2][32][17]
    float* c_sh = (float*)(dsm_l + L_CSH);       // [128]

    // one-time: Wh slice hi/lo (rows r=g*8+q, k)
    for (int i = tid; i < 32 * 512; i += 256) {
        int k = i >> 5, r = i & 31;
        int jcol = (r >> 3) * 512 + bid * 8 + (r & 7);
        float w = Wh[k * G4 + jcol];
        __nv_bfloat16 hi = __float2bfloat16(w);
        float hif = __bfloat162float(hi);
        __nv_bfloat16 lo = __float2bfloat16(w - hif);
        Bh[r * 520 + k] = *(uint16_t*)&hi;
        Bl[r * 520 + k] = *(uint16_t*)&lo;
    }
    if (tid < 128) c_sh[tid] = 0.f;

    const int q = tid & 7, n = tid >> 3;         // gate threads (tid<128)
    const int jglob = bid * 8 + q;

    const int nrow0 = (wid & 3) * 8;             // warp's 8 output rows
    const int kh = wid >> 2;                     // warp's K-half
    const uint32_t a_base_h = smem_to_u32(dsm_l + L_AH);
    const uint32_t a_base_l = smem_to_u32(dsm_l + L_AL);
    const uint32_t a_lane = (uint32_t)((lane & 15) * 520 + (lane >> 4) * 8) * 2;
    const uint32_t b_lane = (uint32_t)((nrow0 + (lane & 7)) * 520 + ((lane >> 3) & 1) * 8) * 2;
    const uint32_t b_base_h = smem_to_u32(dsm_l + L_BH) + b_lane;
    const uint32_t b_base_l = smem_to_u32(dsm_l + L_BL) + b_lane;
    const uint32_t khoff = (uint32_t)(kh * 256) * 2;

    for (int t = 0; t < TSTEPS; ++t) {
        // A fill: vectorized unpack of packed (hi,lo) h into two bf16 tiles [16][520]
        const uint4* src4 = (const uint4*)g_hpk2[t & 1];
        #pragma unroll
        for (int j = 0; j < 8; ++j) {
            int i4 = tid + j * 256;
            int an = i4 >> 7;
            int ak = (i4 << 2) & 511;
            uint4 u = __ldcg(&src4[i4]);
            uint32_t* ah32 = (uint32_t*)(Ah + an * 520 + ak);
            uint32_t* al32 = (uint32_t*)(Al + an * 520 + ak);
            ah32[0] = (u.y & 0xffff0000u) | (u.x >> 16);
            ah32[1] = (u.w & 0xffff0000u) | (u.z >> 16);
            al32[0] = (u.y << 16) | (u.x & 0xffffu);
            al32[1] = (u.w << 16) | (u.z & 0xffffu);
        }
        float xwv[4];
        if (tid < 128) {
            #pragma unroll
            for (int g = 0; g < 4; ++g)
                xwv[g] = g_xw[(size_t)(t * NBATCH + n) * G4 + g * 512 + jglob];
        }
        __syncthreads();

        // MMA: warp computes m16 x n8 over its K-half; 3 hi/lo terms
        {
            float dhh[4], dhl[4], dlh[4];
            #pragma unroll
            for (int e = 0; e < 4; ++e) { dhh[e] = 0.f; dhl[e] = 0.f; dlh[e] = 0.f; }

            #pragma unroll
            for (int s = 0; s < 16; ++s) {
                uint32_t koff = khoff + (uint32_t)(s * 16) * 2;
                uint32_t ah[4], al[4], bh[2], bl[2];
                LDSM_X4(ah, a_base_h + a_lane + koff);
                LDSM_X4(al, a_base_l + a_lane + koff);
                LDSM_X2(bh, b_base_h + koff);
                LDSM_X2(bl, b_base_l + koff);
                MMA16816(dhh, ah, bh[0], bh[1]);
                MMA16816(dhl, ah, bl[0], bl[1]);
                MMA16816(dlh, al, bh[0], bh[1]);
            }
            int m0 = lane >> 2, cc = 2 * (lane & 3);
            float e0 = dhh[0] + dhl[0] + dlh[0];
            float e1 = dhh[1] + dhl[1] + dlh[1];
            float e2 = dhh[2] + dhl[2] + dlh[2];
            float e3 = dhh[3] + dhl[3] + dlh[3];
            float* as = a_sh + kh * 32 * 17;
            as[(nrow0 + cc + 0) * 17 + m0]     = e0;
            as[(nrow0 + cc + 1) * 17 + m0]     = e1;
            as[(nrow0 + cc + 0) * 17 + m0 + 8] = e2;
            as[(nrow0 + cc + 1) * 17 + m0 + 8] = e3;
        }
        __syncthreads();

        // gates: tid<128, (n, q)
        if (tid < 128) {
            float av0 = a_sh[( 0 + q) * 17 + n] + a_sh[(32 * 17) + ( 0 + q) * 17 + n] + xwv[0];
            float av1 = a_sh[( 8 + q) * 17 + n] + a_sh[(32 * 17) + ( 8 + q) * 17 + n] + xwv[1];
            float av2 = a_sh[(16 + q) * 17 + n] + a_sh[(32 * 17) + (16 + q) * 17 + n] + xwv[2];
            float av3 = a_sh[(24 + q) * 17 + n] + a_sh[(32 * 17) + (24 + q) * 17 + n] + xwv[3];
            float ig = sigf(av0), fg = sigf(av1), og = sigf(av2), gg = tanhf_fast(av3);
            float c  = fg * c_sh[tid] + ig * gg;
            float hh = og * tanhf_fast(c);
            c_sh[tid] = c;
            __nv_bfloat16 hi = __float2bfloat16(hh);
            float hif = __bfloat162float(hi);
            __nv_bfloat16 lo = __float2bfloat16(hh - hif);
            g_hpk2[(t & 1) ^ 1][n * HIDDEN + jglob] =
                ((uint32_t)*(uint16_t*)&hi << 16) | *(uint16_t*)&lo;
            g_hb[t * (NBATCH * HIDDEN) + n * HIDDEN + jglob] = hi;
        }
        grid_barrier(t, LCTAS);
    }
}

// ---------------- target logits (bf16 h, consistent with vocab GEMM) ----------------
__global__ void __launch_bounds__(256) tgt_kernel(
    const int* __restrict__ captions, const float* __restrict__ bv)
{
    int wid = threadIdx.x >> 5, lane = threadIdx.x & 31;
    int r = blockIdx.x * 8 + wid;
    int tg = captions[(r & 15) * 257 + (r >> 4) + 1];
    const uint4* hp4 = (const uint4*)(g_hb + (size_t)r * HIDDEN);
    const uint4* wp4 = (const uint4*)(g_wvb + (size_t)tg * HIDDEN);
    float s = 0.f;
    #pragma unroll
    for (int i = 0; i < 2; ++i) {
        uint4 hu = hp4[lane + i * 32];
        uint4 wu = wp4[lane + i * 32];
        s = fmaf(bf16lo_f(hu.x), bf16lo_f(wu.x), s);
        s = fmaf(bf16hi_f(hu.x), bf16hi_f(wu.x), s);
        s = fmaf(bf16lo_f(hu.y), bf16lo_f(wu.y), s);
        s = fmaf(bf16hi_f(hu.y), bf16hi_f(wu.y), s);
        s = fmaf(bf16lo_f(hu.z), bf16lo_f(wu.z), s);
        s = fmaf(bf16hi_f(hu.z), bf16hi_f(wu.z), s);
        s = fmaf(bf16lo_f(hu.w), bf16lo_f(wu.w), s);
        s = fmaf(bf16hi_f(hu.w), bf16hi_f(wu.w), s);
    }
    #pragma unroll
    for (int o = 16; o > 0; o >>= 1) s += __shfl_xor_sync(0xffffffffu, s, o);
    if (lane == 0) g_lt[r] = s + bv[tg];
}

// ---------------- vocab v3: flat jobs over 148 CTAs, bf16 mma + streaming exp-sum -----
#define V_A_STRIDE 520
#define V_B_OFF    133120
#define V_B_SZ     18432
#define V_B_STRIDE 72
#define V_RED_OFF  169984
#define V_SMEM     171008
extern __shared__ __align__(16) char dsm_v[];
__global__ void __launch_bounds__(256, 1) vocab_kernel() {
    __nv_bfloat16* As = (__nv_bfloat16*)dsm_v;
    float* red = (float*)(dsm_v + V_RED_OFF);
    const int tid = threadIdx.x, lane = tid & 31, wid = tid >> 5;
    const int wm = wid >> 1, wn = wid & 1;

    const int start = (int)(((long long)blockIdx.x * NJOBS) / VCTAS);
    const int end   = (int)(((long long)(blockIdx.x + 1) * NJOBS) / VCTAS);

    const uint32_t a_base = smem_to_u32(dsm_v);
    const uint32_t a_lane = (uint32_t)((lane & 15) * V_A_STRIDE + (lane >> 4) * 8) * 2;
    const int bq = lane >> 3;
    const uint32_t b_lane = (uint32_t)(((bq >> 1) * 8 + (lane & 7)) * V_B_STRIDE + (bq & 1) * 8) * 2;

    float rs[2][2] = {{0.f, 0.f}, {0.f, 0.f}};
    int cur_mblk = -1;

    for (int j = start; j < end; ++j) {
        const int mblk = j / NTILN, nt = j % NTILN;

        if (mblk != cur_mblk) {
            if (cur_mblk >= 0) {
                #pragma unroll
                for (int mt = 0; mt < 2; ++mt)
                    #pragma unroll
                    for (int rh = 0; rh < 2; ++rh) {
                        float v = rs[mt][rh];
                        v += __shfl_xor_sync(0xffffffffu, v, 1);
                        v += __shfl_xor_sync(0xffffffffu, v, 2);
                        if ((lane & 3) == 0)
                            red[(wm * 32 + mt * 16 + rh * 8 + (lane >> 2)) * 2 + wn] = v;
                        rs[mt][rh] = 0.f;
                    }
                __syncthreads();
                if (tid < 128)
                    atomicAdd(&g_ps_flat[cur_mblk * 128 + tid], red[tid * 2] + red[tid * 2 + 1]);
            }
            __syncthreads();
            const uint4* src = (const uint4*)(g_hb + (size_t)(mblk * 128) * HIDDEN);
            for (int i = tid; i < 8192; i += 256) {
                int r = i >> 6, u = i & 63;
                *(uint4*)(As + r * V_A_STRIDE + u * 8) = src[i];
            }
            __syncthreads();
            cur_mblk = mblk;
        }

        const int nbase = nt * 128;
        float bb[16];
        {
            int cb = nbase + wn * 64 + (lane & 3) * 2;
            #pragma unroll
            for (int nt2 = 0; nt2 < 8; ++nt2) {
                bb[nt2 * 2 + 0] = g_bv2[cb + nt2 * 8 + 0];
                bb[nt2 * 2 + 1] = g_bv2[cb + nt2 * 8 + 1];
            }
        }
        float d[2][8][4];
        #pragma unroll
        for (int mt = 0; mt < 2; ++mt)
            #pragma unroll
            for (int nt2 = 0; nt2 < 8; ++nt2)
                #pragma unroll
                for (int e = 0; e < 4; ++e) d[mt][nt2][e] = 0.f;

        uint4 ld[4];
        #pragma unroll
        for (int qq = 0; qq < 4; ++qq) {
            int i = qq * 256 + tid;
            int n = i >> 3, u = i & 7;
            ld[qq] = *(const uint4*)(g_wvb + (size_t)(nbase + n) * HIDDEN + u * 8);
        }
        #pragma unroll
        for (int qq = 0; qq < 4; ++qq) {
            int i = qq * 256 + tid;
            int n = i >> 3, u = i & 7;
            *(uint4*)((__nv_bfloat16*)(dsm_v + V_B_OFF) + n * V_B_STRIDE + u * 8) = ld[qq];
        }
        __syncthreads();

        for (int kc = 0; kc < 8; ++kc) {
            if (kc < 7) {
                #pragma unroll
                for (int qq = 0; qq < 4; ++qq) {
                    int i = qq * 256 + tid;
                    int n = i >> 3, u = i & 7;
                    ld[qq] = *(const uint4*)(g_wvb + (size_t)(nbase + n) * HIDDEN + (kc + 1) * 64 + u * 8);
                }
            }
            const uint32_t b_base = smem_to_u32(dsm_v + V_B_OFF + (kc & 1) * V_B_SZ) + (uint32_t)(wn * 64 * V_B_STRIDE) * 2;
            #pragma unroll
            for (int k16 = 0; k16 < 4; ++k16) {
                uint32_t a[2][4];
                #pragma unroll
                for (int mt = 0; mt < 2; ++mt) {
                    uint32_t aaddr = a_base + a_lane +
                        (uint32_t)((wm * 32 + mt * 16) * V_A_STRIDE + kc * 64 + k16 * 16) * 2;
                    LDSM_X4(a[mt], aaddr);
                }
                #pragma unroll
                for (int np = 0; np < 4; ++np) {
                    uint32_t b[4];
                    uint32_t baddr = b_base + b_lane + (uint32_t)(np * 16 * V_B_STRIDE + k16 * 16) * 2;
                    LDSM_X4(b, baddr);
                    MMA16816(d[0][np * 2 + 0], a[0], b[0], b[1]);
                    MMA16816(d[0][np * 2 + 1], a[0], b[2], b[3]);
                    MMA16816(d[1][np * 2 + 0], a[1], b[0], b[1]);
                    MMA16816(d[1][np * 2 + 1], a[1], b[2], b[3]);
                }
            }
            if (kc < 7) {
                __nv_bfloat16* dst = (__nv_bfloat16*)(dsm_v + V_B_OFF + ((kc + 1) & 1) * V_B_SZ);
                #pragma unroll
                for (int qq = 0; qq < 4; ++qq) {
                    int i = qq * 256 + tid;
                    int n = i >> 3, u = i & 7;
                    *(uint4*)(dst + n * V_B_STRIDE + u * 8) = ld[qq];
                }
            }
            __syncthreads();
        }

        #pragma unroll
        for (int mt = 0; mt < 2; ++mt)
            #pragma unroll
            for (int rh = 0; rh < 2; ++rh) {
                float s = 0.f;
                #pragma unroll
                for (int nt2 = 0; nt2 < 8; ++nt2) {
                    s += exp2_fast(fmaf(d[mt][nt2][rh * 2 + 0], LOG2E, bb[nt2 * 2 + 0]));
                    s += exp2_fast(fmaf(d[mt][nt2][rh * 2 + 1], LOG2E, bb[nt2 * 2 + 1]));
                }
                rs[mt][rh] += s;
            }
    }

    if (cur_mblk >= 0) {
        #pragma unroll
        for (int mt = 0; mt < 2; ++mt)
            #pragma unroll
            for (int rh = 0; rh < 2; ++rh) {
                float v = rs[mt][rh];
                v += __shfl_xor_sync(0xffffffffu, v, 1);
                v += __shfl_xor_sync(0xffffffffu, v, 2);
                if ((lane & 3) == 0)
                    red[(wm * 32 + mt * 16 + rh * 8 + (lane >> 2)) * 2 + wn] = v;
            }
        __syncthreads();
        if (tid < 128)
            atomicAdd(&g_ps_flat[cur_mblk * 128 + tid], red[tid * 2] + red[tid * 2 + 1]);
    }
}

// ---------------- combine ----------------
__global__ void __launch_bounds__(1024) combine_kernel(
    const int* __restrict__ captions, float* __restrict__ out)
{
    __shared__ float sh[1024];
    int tid = threadIdx.x;
    float local = 0.f;
    for (int r = tid; r < MROWS; r += 1024) {
        float S = g_ps_flat[r];
        int tg = captions[(r & 15) * 257 + (r >> 4) + 1];
        if (tg != 0) local += logf(S) - g_lt[r];
    }
    sh[tid] = local;
    __syncthreads();
    for (int o = 512; o > 0; o >>= 1) {
        if (tid < o) sh[tid] += sh[tid + o];
        __syncthreads();
    }
    if (tid == 0) out[0] = sh[0] * (1.f / NBATCH);
}

// ---------------- launch ----------------
extern "C" void kernel_launch(void* const* d_in, const int* in_sizes, int n_in,
                              void* d_out, int out_size) {
    const int*   captions = (const int*)d_in[0];
    const float* W_embed  = (const float*)d_in[1];
    const float* Wx       = (const float*)d_in[2];
    const float* Wh       = (const float*)d_in[3];
    const float* b        = (const float*)d_in[4];
    const float* W_vocab  = (const float*)d_in[5];
    const float* b_vocab  = (const float*)d_in[6];
    const float* h_init   = (const float*)d_in[7];

    cudaFuncSetAttribute(lstm_kernel,      cudaFuncAttributeMaxDynamicSharedMemorySize, L_SMEM);
    cudaFuncSetAttribute(vocab_kernel,     cudaFuncAttributeMaxDynamicSharedMemorySize, V_SMEM);
    cudaFuncSetAttribute(embed_mma_kernel, cudaFuncAttributeMaxDynamicSharedMemorySize, E_SMEM);

    init_kernel<<<32, 256>>>(h_init, b_vocab);
    prep_kernel<<<768, 256>>>(captions, W_embed, Wx);
    embed_mma_kernel<<<512, 256, E_SMEM>>>(b);
    lstm_kernel<<<LCTAS, 256, L_SMEM>>>(Wh);                   // 4th launch -> profiled
    conv_wv_kernel<<<dim3(VOCABSZ / 32, HIDDEN / 32), 256>>>(W_vocab);
    tgt_kernel<<<512, 256>>>(captions, b_vocab);
    vocab_kernel<<<VCTAS, 256, V_SMEM>>>();
    combine_kernel<<<1, 1024>>>(captions, (float*)d_out);
}

// round 17
// speedup vs baseline: 1.0032x; 1.0032x over previous
#include <cuda_runtime.h>
#include <cuda_bf16.h>
#include <cstdint>
#include <math.h>

#define VOCABSZ 32000
#define VPAD    32128
#define WORDVEC 256
#define HIDDEN  512
#define TSTEPS  256
#define NBATCH  16
#define G4      2048
#define MROWS   4096
#define NTILN   251          // VPAD / 128
#define NJOBS   (32 * NTILN) // 8032
#define VCTAS   148
#define LCTAS   64
#define LOG2E   1.44269504f

// ---------------- device scratch ----------------
__device__ float          g_xw[TSTEPS * NBATCH * G4];
__device__ __nv_bfloat16  g_hb[MROWS * HIDDEN];            // bf16 h history (written by lstm)
__device__ __nv_bfloat16  g_wvb[(size_t)VPAD * HIDDEN];    // Wv^T bf16 [v][k]
__device__ __nv_bfloat16  g_xb[MROWS * WORDVEC];           // gathered embeddings bf16
__device__ __nv_bfloat16  g_wxT[G4 * WORDVEC];             // Wx^T bf16
__device__ float          g_bv2[VPAD];                     // bv * LOG2E (pad = -120)
__device__ uint32_t       g_hpk2[2][NBATCH * HIDDEN];      // packed (hi,lo) bf16 h state
__device__ unsigned       g_barc[TSTEPS];
__device__ float          g_ps_flat[MROWS];                // per-row exp-sums (atomic)
__device__ float          g_lt[MROWS];

// ---------------- helpers ----------------
__device__ __forceinline__ float sigf(float x) { return __fdividef(1.f, 1.f + __expf(-x)); }
__device__ __forceinline__ float tanhf_fast(float x) { return __fdividef(2.f, 1.f + __expf(-2.f * x)) - 1.f; }
__device__ __forceinline__ uint32_t smem_to_u32(const void* p) {
    uint32_t a;
    asm("{ .reg .u64 t; cvta.to.shared.u64 t, %1; cvt.u32.u64 %0, t; }" : "=r"(a) : "l"(p));
    return a;
}
__device__ __forceinline__ float bf16lo_f(uint32_t u) { return __uint_as_float(u << 16); }
__device__ __forceinline__ float bf16hi_f(uint32_t u) { return __uint_as_float(u & 0xffff0000u); }
#define LDSM_X4(r, addr) asm volatile( \
    "ldmatrix.sync.aligned.m8n8.x4.shared.b16 {%0,%1,%2,%3}, [%4];" \
    : "=r"((r)[0]), "=r"((r)[1]), "=r"((r)[2]), "=r"((r)[3]) : "r"(addr))
#define LDSM_X2(r, addr) asm volatile( \
    "ldmatrix.sync.aligned.m8n8.x2.shared.b16 {%0,%1}, [%2];" \
    : "=r"((r)[0]), "=r"((r)[1]) : "r"(addr))
#define MMA16816(d, a, b0, b1) asm volatile( \
    "mma.sync.aligned.m16n8k16.row.col.f32.bf16.bf16.f32 " \
    "{%0,%1,%2,%3}, {%4,%5,%6,%7}, {%8,%9}, {%0,%1,%2,%3};" \
    : "+f"((d)[0]), "+f"((d)[1]), "+f"((d)[2]), "+f"((d)[3]) \
    : "r"((a)[0]), "r"((a)[1]), "r"((a)[2]), "r"((a)[3]), "r"(b0), "r"(b1))

__device__ __forceinline__ float exp2_fast(float t) {
    int i = __float2int_rn(t);
    float f = t - (float)i;
    float p = fmaf(f, 0.00133335581f, 0.00961812911f);
    p = fmaf(f, p, 0.0555041087f);
    p = fmaf(f, p, 0.240226507f);
    p = fmaf(f, p, 0.693147181f);
    p = fmaf(f, p, 1.0f);
    return __int_as_float(__float_as_int(p) + (i << 23));
}

__device__ __forceinline__ void grid_barrier(int idx, unsigned nblocks) {
    __threadfence();
    __syncthreads();
    if (threadIdx.x == 0) {
        atomicAdd(&g_barc[idx], 1u);
        volatile unsigned* p = &g_barc[idx];
        while (*p < nblocks) { }
        __threadfence();
    }
    __syncthreads();
}

// ---------------- init (every replay) ----------------
__global__ void __launch_bounds__(256) init_kernel(
    const float* __restrict__ h_init, const float* __restrict__ bv)
{
    int gid = blockIdx.x * 256 + threadIdx.x;            // 8192 threads
    if (gid < TSTEPS) g_barc[gid] = 0u;
    if (gid < MROWS) g_ps_flat[gid] = 0.f;
    if (gid < NBATCH * HIDDEN) {
        int k = gid & 511;
        float v = h_init[k];
        __nv_bfloat16 hi = __float2bfloat16(v);
        float hif = __bfloat162float(hi);
        __nv_bfloat16 lo = __float2bfloat16(v - hif);
        g_hpk2[0][gid] = ((uint32_t)*(uint16_t*)&hi << 16) | *(uint16_t*)&lo;
    }
    for (int j = gid; j < (VPAD - VOCABSZ) * HIDDEN; j += 8192)
        g_wvb[(size_t)VOCABSZ * HIDDEN + j] = __float2bfloat16(0.f);
    for (int j = gid; j < VPAD; j += 8192)
        g_bv2[j] = (j < VOCABSZ) ? bv[j] * LOG2E : -120.f;
}

// ---------------- prep: gather embeddings + Wx transpose (fused) ----------------
__global__ void __launch_bounds__(256) prep_kernel(
    const int* __restrict__ captions, const float* __restrict__ W_embed,
    const float* __restrict__ Wx)
{
    __shared__ float sh[32 * 33];
    if (blockIdx.x < 256) {
        int gid = blockIdx.x * 256 + threadIdx.x;
        int idx = gid * 4;
        int r = idx >> 8, d = idx & 255;
        int tok = captions[(r & 15) * 257 + (r >> 4)];
        float4 v = *(const float4*)&W_embed[tok * WORDVEC + d];
        __nv_bfloat16 o[4];
        o[0] = __float2bfloat16(v.x); o[1] = __float2bfloat16(v.y);
        o[2] = __float2bfloat16(v.z); o[3] = __float2bfloat16(v.w);
        *(uint2*)&g_xb[idx] = *(const uint2*)o;
    } else {
        int bid2 = blockIdx.x - 256;
        int n0 = (bid2 & 63) * 32, k0 = (bid2 >> 6) * 32;
        int tx = threadIdx.x & 31, ty = threadIdx.x >> 5;
        #pragma unroll
        for (int i = 0; i < 4; ++i) {
            int k = ty + i * 8;
            sh[k * 33 + tx] = Wx[(k0 + k) * G4 + n0 + tx];
        }
        __syncthreads();
        #pragma unroll
        for (int i = 0; i < 4; ++i) {
            int n = ty + i * 8;
            g_wxT[(n0 + n) * WORDVEC + k0 + tx] = __float2bfloat16(sh[tx * 33 + n]);
        }
    }
}

// ---------------- Wv transpose + bf16 ----------------
__global__ void __launch_bounds__(256) conv_wv_kernel(const float* __restrict__ Wv) {
    __shared__ float sh[32 * 33];
    int n0 = blockIdx.x * 32, k0 = blockIdx.y * 32;
    int tx = threadIdx.x & 31, ty = threadIdx.x >> 5;
    #pragma unroll
    for (int i = 0; i < 4; ++i) {
        int k = ty + i * 8;
        sh[k * 33 + tx] = Wv[(size_t)(k0 + k) * VOCABSZ + n0 + tx];
    }
    __syncthreads();
    #pragma unroll
    for (int i = 0; i < 4; ++i) {
        int n = ty + i * 8;
        g_wvb[(size_t)(n0 + n) * HIDDEN + k0 + tx] = __float2bfloat16(sh[tx * 33 + n]);
    }
}

// ---------------- embed GEMM (bf16 mma.sync) ----------------
#define E_A_STRIDE 264
#define E_B_OFF    67584
#define E_SMEM     135168
extern __shared__ __align__(16) char dsm_e[];
__global__ void __launch_bounds__(256, 1) embed_mma_kernel(const float* __restrict__ b) {
    __nv_bfloat16* As = (__nv_bfloat16*)dsm_e;
    __nv_bfloat16* Bs = (__nv_bfloat16*)(dsm_e + E_B_OFF);
    const int tid = threadIdx.x, lane = tid & 31, wid = tid >> 5;
    const int wm = wid >> 1, wn = wid & 1;
    const int mblk = blockIdx.x >> 4, nblk = blockIdx.x & 15;

    const uint4* asrc = (const uint4*)(g_xb + mblk * 128 * WORDVEC);
    const uint4* bsrc = (const uint4*)(g_wxT + nblk * 128 * WORDVEC);
    #pragma unroll
    for (int q = 0; q < 16; ++q) {
        int i = q * 256 + tid;
        int r = i >> 5, u = i & 31;
        *(uint4*)(As + r * E_A_STRIDE + u * 8) = asrc[i];
        *(uint4*)(Bs + r * E_A_STRIDE + u * 8) = bsrc[i];
    }
    __syncthreads();

    const uint32_t a_base = smem_to_u32(As);
    const uint32_t a_lane = (uint32_t)((lane & 15) * E_A_STRIDE + (lane >> 4) * 8) * 2;
    const int bq = lane >> 3;
    const uint32_t b_lane = (uint32_t)(((bq >> 1) * 8 + (lane & 7)) * E_A_STRIDE + (bq & 1) * 8) * 2;
    const uint32_t b_base = smem_to_u32(Bs) + (uint32_t)(wn * 64 * E_A_STRIDE) * 2;

    float d[2][8][4];
    #pragma unroll
    for (int mt = 0; mt < 2; ++mt)
        #pragma unroll
        for (int nt = 0; nt < 8; ++nt)
            #pragma unroll
            for (int e = 0; e < 4; ++e) d[mt][nt][e] = 0.f;

    #pragma unroll
    for (int k16 = 0; k16 < 16; ++k16) {
        const uint32_t koff = (uint32_t)(k16 * 16) * 2;
        uint32_t a[2][4];
        #pragma unroll
        for (int mt = 0; mt < 2; ++mt) {
            LDSM_X4(a[mt], a_base + a_lane + (uint32_t)((wm * 32 + mt * 16) * E_A_STRIDE) * 2 + koff);
        }
        #pragma unroll
        for (int np = 0; np < 4; ++np) {
            uint32_t bb[4];
            LDSM_X4(bb, b_base + b_lane + (uint32_t)(np * 16 * E_A_STRIDE) * 2 + koff);
            MMA16816(d[0][np * 2 + 0], a[0], bb[0], bb[1]);
            MMA16816(d[0][np * 2 + 1], a[0], bb[2], bb[3]);
            MMA16816(d[1][np * 2 + 0], a[1], bb[0], bb[1]);
            MMA16816(d[1][np * 2 + 1], a[1], bb[2], bb[3]);
        }
    }

    const int cbase = nblk * 128 + wn * 64 + (lane & 3) * 2;
    #pragma unroll
    for (int mt = 0; mt < 2; ++mt)
        #pragma unroll
        for (int rh = 0; rh < 2; ++rh) {
            int row = mblk * 128 + wm * 32 + mt * 16 + rh * 8 + (lane >> 2);
            #pragma unroll
            for (int nt = 0; nt < 8; ++nt) {
                int c = cbase + nt * 8;
                float2 v;
                v.x = d[mt][nt][rh * 2 + 0] + b[c];
                v.y = d[mt][nt][rh * 2 + 1] + b[c + 1];
                *(float2*)&g_xw[(size_t)row * G4 + c] = v;
            }
        }
}

// ---------------- persistent LSTM v4: 64 blocks, warp = (n8 rows) x (K-half) ----------
// Block owns 8 hidden units (32 gate-cols: row r = g*8+q, jcol = g*512 + bid*8 + q).
// 8 warps: rows (w&3)*8..+7, K-half (w>>2)*256. a_sh[2][32][17] partials, gates sum.
#define L_BH   0
#define L_BL   33280
#define L_AH   66560
#define L_AL   83200
#define L_ASH  99840
#define L_CSH  104192
#define L_SMEM 104704
extern __shared__ __align__(16) char dsm_l[];
__global__ void __launch_bounds__(256, 1) lstm_kernel(const float* __restrict__ Wh) {
    const int bid = blockIdx.x, tid = threadIdx.x;
    const int lane = tid & 31, wid = tid >> 5;
    uint16_t* Bh = (uint16_t*)(dsm_l + L_BH);    // [32][520]
    uint16_t* Bl = (uint16_t*)(dsm_l + L_BL);
    uint16_t* Ah = (uint16_t*)(dsm_l + L_AH);    // [16][520]
    uint16_t* Al = (uint16_t*)(dsm_l + L_AL);
    float* a_sh = (float*)(dsm_l + L_ASH);       // [2][32][17]
    float* c_sh = (float*)(dsm_l + L_CSH);       // [128]

    // one-time: Wh slice hi/lo (rows r=g*8+q, k)
    for (int i = tid; i < 32 * 512; i += 256) {
        int k = i >> 5, r = i & 31;
        int jcol = (r >> 3) * 512 + bid * 8 + (r & 7);
        float w = Wh[k * G4 + jcol];
        __nv_bfloat16 hi = __float2bfloat16(w);
        float hif = __bfloat162float(hi);
        __nv_bfloat16 lo = __float2bfloat16(w - hif);
        Bh[r * 520 + k] = *(uint16_t*)&hi;
        Bl[r * 520 + k] = *(uint16_t*)&lo;
    }
    if (tid < 128) c_sh[tid] = 0.f;

    const int q = tid & 7, n = tid >> 3;         // gate threads (tid<128)
    const int jglob = bid * 8 + q;

    const int nrow0 = (wid & 3) * 8;             // warp's 8 output rows
    const int kh = wid >> 2;                     // warp's K-half
    const uint32_t a_base_h = smem_to_u32(dsm_l + L_AH);
    const uint32_t a_base_l = smem_to_u32(dsm_l + L_AL);
    const uint32_t a_lane = (uint32_t)((lane & 15) * 520 + (lane >> 4) * 8) * 2;
    const uint32_t b_lane = (uint32_t)((nrow0 + (lane & 7)) * 520 + ((lane >> 3) & 1) * 8) * 2;
    const uint32_t b_base_h = smem_to_u32(dsm_l + L_BH) + b_lane;
    const uint32_t b_base_l = smem_to_u32(dsm_l + L_BL) + b_lane;
    const uint32_t khoff = (uint32_t)(kh * 256) * 2;

    for (int t = 0; t < TSTEPS; ++t) {
        // A fill: vectorized unpack of packed (hi,lo) h into two bf16 tiles [16][520]
        const uint4* src4 = (const uint4*)g_hpk2[t & 1];
        #pragma unroll
        for (int j = 0; j < 8; ++j) {
            int i4 = tid + j * 256;
            int an = i4 >> 7;
            int ak = (i4 << 2) & 511;
            uint4 u = __ldcg(&src4[i4]);
            uint32_t* ah32 = (uint32_t*)(Ah + an * 520 + ak);
            uint32_t* al32 = (uint32_t*)(Al + an * 520 + ak);
            ah32[0] = (u.y & 0xffff0000u) | (u.x >> 16);
            ah32[1] = (u.w & 0xffff0000u) | (u.z >> 16);
            al32[0] = (u.y << 16) | (u.x & 0xffffu);
            al32[1] = (u.w << 16) | (u.z & 0xffffu);
        }
        float xwv[4];
        if (tid < 128) {
            #pragma unroll
            for (int g = 0; g < 4; ++g)
                xwv[g] = g_xw[(size_t)(t * NBATCH + n) * G4 + g * 512 + jglob];
        }
        __syncthreads();

        // MMA: warp computes m16 x n8 over its K-half; 3 hi/lo terms
        {
            float dhh[4], dhl[4], dlh[4];
            #pragma unroll
            for (int e = 0; e < 4; ++e) { dhh[e] = 0.f; dhl[e] = 0.f; dlh[e] = 0.f; }

            #pragma unroll
            for (int s = 0; s < 16; ++s) {
                uint32_t koff = khoff + (uint32_t)(s * 16) * 2;
                uint32_t ah[4], al[4], bh[2], bl[2];
                LDSM_X4(ah, a_base_h + a_lane + koff);
                LDSM_X4(al, a_base_l + a_lane + koff);
                LDSM_X2(bh, b_base_h + koff);
                LDSM_X2(bl, b_base_l + koff);
                MMA16816(dhh, ah, bh[0], bh[1]);
                MMA16816(dhl, ah, bl[0], bl[1]);
                MMA16816(dlh, al, bh[0], bh[1]);
            }
            int m0 = lane >> 2, cc = 2 * (lane & 3);
            float e0 = dhh[0] + dhl[0] + dlh[0];
            float e1 = dhh[1] + dhl[1] + dlh[1];
            float e2 = dhh[2] + dhl[2] + dlh[2];
            float e3 = dhh[3] + dhl[3] + dlh[3];
            float* as = a_sh + kh * 32 * 17;
            as[(nrow0 + cc + 0) * 17 + m0]     = e0;
            as[(nrow0 + cc + 1) * 17 + m0]     = e1;
            as[(nrow0 + cc + 0) * 17 + m0 + 8] = e2;
            as[(nrow0 + cc + 1) * 17 + m0 + 8] = e3;
        }
        __syncthreads();

        // gates: tid<128, (n, q)
        if (tid < 128) {
            float av0 = a_sh[( 0 + q) * 17 + n] + a_sh[(32 * 17) + ( 0 + q) * 17 + n] + xwv[0];
            float av1 = a_sh[( 8 + q) * 17 + n] + a_sh[(32 * 17) + ( 8 + q) * 17 + n] + xwv[1];
            float av2 = a_sh[(16 + q) * 17 + n] + a_sh[(32 * 17) + (16 + q) * 17 + n] + xwv[2];
            float av3 = a_sh[(24 + q) * 17 + n] + a_sh[(32 * 17) + (24 + q) * 17 + n] + xwv[3];
            float ig = sigf(av0), fg = sigf(av1), og = sigf(av2), gg = tanhf_fast(av3);
            float c  = fg * c_sh[tid] + ig * gg;
            float hh = og * tanhf_fast(c);
            c_sh[tid] = c;
            __nv_bfloat16 hi = __float2bfloat16(hh);
            float hif = __bfloat162float(hi);
            __nv_bfloat16 lo = __float2bfloat16(hh - hif);
            g_hpk2[(t & 1) ^ 1][n * HIDDEN + jglob] =
                ((uint32_t)*(uint16_t*)&hi << 16) | *(uint16_t*)&lo;
            g_hb[t * (NBATCH * HIDDEN) + n * HIDDEN + jglob] = hi;
        }
        grid_barrier(t, LCTAS);
    }
}

// ---------------- target logits (bf16 h, consistent with vocab GEMM) ----------------
__global__ void __launch_bounds__(256) tgt_kernel(
    const int* __restrict__ captions, const float* __restrict__ bv)
{
    int wid = threadIdx.x >> 5, lane = threadIdx.x & 31;
    int r = blockIdx.x * 8 + wid;
    int tg = captions[(r & 15) * 257 + (r >> 4) + 1];
    const uint4* hp4 = (const uint4*)(g_hb + (size_t)r * HIDDEN);
    const uint4* wp4 = (const uint4*)(g_wvb + (size_t)tg * HIDDEN);
    float s = 0.f;
    #pragma unroll
    for (int i = 0; i < 2; ++i) {
        uint4 hu = hp4[lane + i * 32];
        uint4 wu = wp4[lane + i * 32];
        s = fmaf(bf16lo_f(hu.x), bf16lo_f(wu.x), s);
        s = fmaf(bf16hi_f(hu.x), bf16hi_f(wu.x), s);
        s = fmaf(bf16lo_f(hu.y), bf16lo_f(wu.y), s);
        s = fmaf(bf16hi_f(hu.y), bf16hi_f(wu.y), s);
        s = fmaf(bf16lo_f(hu.z), bf16lo_f(wu.z), s);
        s = fmaf(bf16hi_f(hu.z), bf16hi_f(wu.z), s);
        s = fmaf(bf16lo_f(hu.w), bf16lo_f(wu.w), s);
        s = fmaf(bf16hi_f(hu.w), bf16hi_f(wu.w), s);
    }
    #pragma unroll
    for (int o = 16; o > 0; o >>= 1) s += __shfl_xor_sync(0xffffffffu, s, o);
    if (lane == 0) g_lt[r] = s + bv[tg];
}

// ---------------- vocab v3: flat jobs over 148 CTAs, bf16 mma + streaming exp-sum -----
#define V_A_STRIDE 520
#define V_B_OFF    133120
#define V_B_SZ     18432
#define V_B_STRIDE 72
#define V_RED_OFF  169984
#define V_SMEM     171008
extern __shared__ __align__(16) char dsm_v[];
__global__ void __launch_bounds__(256, 1) vocab_kernel() {
    __nv_bfloat16* As = (__nv_bfloat16*)dsm_v;
    float* red = (float*)(dsm_v + V_RED_OFF);
    const int tid = threadIdx.x, lane = tid & 31, wid = tid >> 5;
    const int wm = wid >> 1, wn = wid & 1;

    const int start = (int)(((long long)blockIdx.x * NJOBS) / VCTAS);
    const int end   = (int)(((long long)(blockIdx.x + 1) * NJOBS) / VCTAS);

    const uint32_t a_base = smem_to_u32(dsm_v);
    const uint32_t a_lane = (uint32_t)((lane & 15) * V_A_STRIDE + (lane >> 4) * 8) * 2;
    const int bq = lane >> 3;
    const uint32_t b_lane = (uint32_t)(((bq >> 1) * 8 + (lane & 7)) * V_B_STRIDE + (bq & 1) * 8) * 2;

    float rs[2][2] = {{0.f, 0.f}, {0.f, 0.f}};
    int cur_mblk = -1;

    for (int j = start; j < end; ++j) {
        const int mblk = j / NTILN, nt = j % NTILN;

        if (mblk != cur_mblk) {
            if (cur_mblk >= 0) {
                #pragma unroll
                for (int mt = 0; mt < 2; ++mt)
                    #pragma unroll
                    for (int rh = 0; rh < 2; ++rh) {
                        float v = rs[mt][rh];
                        v += __shfl_xor_sync(0xffffffffu, v, 1);
                        v += __shfl_xor_sync(0xffffffffu, v, 2);
                        if ((lane & 3) == 0)
                            red[(wm * 32 + mt * 16 + rh * 8 + (lane >> 2)) * 2 + wn] = v;
                        rs[mt][rh] = 0.f;
                    }
                __syncthreads();
                if (tid < 128)
                    atomicAdd(&g_ps_flat[cur_mblk * 128 + tid], red[tid * 2] + red[tid * 2 + 1]);
            }
            __syncthreads();
            const uint4* src = (const uint4*)(g_hb + (size_t)(mblk * 128) * HIDDEN);
            for (int i = tid; i < 8192; i += 256) {
                int r = i >> 6, u = i & 63;
                *(uint4*)(As + r * V_A_STRIDE + u * 8) = src[i];
            }
            __syncthreads();
            cur_mblk = mblk;
        }

        const int nbase = nt * 128;
        float bb[16];
        {
            int cb = nbase + wn * 64 + (lane & 3) * 2;
            #pragma unroll
            for (int nt2 = 0; nt2 < 8; ++nt2) {
                bb[nt2 * 2 + 0] = g_bv2[cb + nt2 * 8 + 0];
                bb[nt2 * 2 + 1] = g_bv2[cb + nt2 * 8 + 1];
            }
        }
        float d[2][8][4];
        #pragma unroll
        for (int mt = 0; mt < 2; ++mt)
            #pragma unroll
            for (int nt2 = 0; nt2 < 8; ++nt2)
                #pragma unroll
                for (int e = 0; e < 4; ++e) d[mt][nt2][e] = 0.f;

        uint4 ld[4];
        #pragma unroll
        for (int qq = 0; qq < 4; ++qq) {
            int i = qq * 256 + tid;
            int n = i >> 3, u = i & 7;
            ld[qq] = *(const uint4*)(g_wvb + (size_t)(nbase + n) * HIDDEN + u * 8);
        }
        #pragma unroll
        for (int qq = 0; qq < 4; ++qq) {
            int i = qq * 256 + tid;
            int n = i >> 3, u = i & 7;
            *(uint4*)((__nv_bfloat16*)(dsm_v + V_B_OFF) + n * V_B_STRIDE + u * 8) = ld[qq];
        }
        __syncthreads();

        for (int kc = 0; kc < 8; ++kc) {
            if (kc < 7) {
                #pragma unroll
                for (int qq = 0; qq < 4; ++qq) {
                    int i = qq * 256 + tid;
                    int n = i >> 3, u = i & 7;
                    ld[qq] = *(const uint4*)(g_wvb + (size_t)(nbase + n) * HIDDEN + (kc + 1) * 64 + u * 8);
                }
            }
            const uint32_t b_base = smem_to_u32(dsm_v + V_B_OFF + (kc & 1) * V_B_SZ) + (uint32_t)(wn * 64 * V_B_STRIDE) * 2;
            #pragma unroll
            for (int k16 = 0; k16 < 4; ++k16) {
                uint32_t a[2][4];
                #pragma unroll
                for (int mt = 0; mt < 2; ++mt) {
                    uint32_t aaddr = a_base + a_lane +
                        (uint32_t)((wm * 32 + mt * 16) * V_A_STRIDE + kc * 64 + k16 * 16) * 2;
                    LDSM_X4(a[mt], aaddr);
                }
                #pragma unroll
                for (int np = 0; np < 4; ++np) {
                    uint32_t b[4];
                    uint32_t baddr = b_base + b_lane + (uint32_t)(np * 16 * V_B_STRIDE + k16 * 16) * 2;
                    LDSM_X4(b, baddr);
                    MMA16816(d[0][np * 2 + 0], a[0], b[0], b[1]);
                    MMA16816(d[0][np * 2 + 1], a[0], b[2], b[3]);
                    MMA16816(d[1][np * 2 + 0], a[1], b[0], b[1]);
                    MMA16816(d[1][np * 2 + 1], a[1], b[2], b[3]);
                }
            }
            if (kc < 7) {
                __nv_bfloat16* dst = (__nv_bfloat16*)(dsm_v + V_B_OFF + ((kc + 1) & 1) * V_B_SZ);
                #pragma unroll
                for (int qq = 0; qq < 4; ++qq) {
                    int i = qq * 256 + tid;
                    int n = i >> 3, u = i & 7;
                    *(uint4*)(dst + n * V_B_STRIDE + u * 8) = ld[qq];
                }
            }
            __syncthreads();
        }

        #pragma unroll
        for (int mt = 0; mt < 2; ++mt)
            #pragma unroll
            for (int rh = 0; rh < 2; ++rh) {
                float s = 0.f;
                #pragma unroll
                for (int nt2 = 0; nt2 < 8; ++nt2) {
                    s += exp2_fast(fmaf(d[mt][nt2][rh * 2 + 0], LOG2E, bb[nt2 * 2 + 0]));
                    s += exp2_fast(fmaf(d[mt][nt2][rh * 2 + 1], LOG2E, bb[nt2 * 2 + 1]));
                }
                rs[mt][rh] += s;
            }
    }

    if (cur_mblk >= 0) {
        #pragma unroll
        for (int mt = 0; mt < 2; ++mt)
            #pragma unroll
            for (int rh = 0; rh < 2; ++rh) {
                float v = rs[mt][rh];
                v += __shfl_xor_sync(0xffffffffu, v, 1);
                v += __shfl_xor_sync(0xffffffffu, v, 2);
                if ((lane & 3) == 0)
                    red[(wm * 32 + mt * 16 + rh * 8 + (lane >> 2)) * 2 + wn] = v;
            }
        __syncthreads();
        if (tid < 128)
            atomicAdd(&g_ps_flat[cur_mblk * 128 + tid], red[tid * 2] + red[tid * 2 + 1]);
    }
}

// ---------------- combine ----------------
__global__ void __launch_bounds__(1024) combine_kernel(
    const int* __restrict__ captions, float* __restrict__ out)
{
    __shared__ float sh[1024];
    int tid = threadIdx.x;
    float local = 0.f;
    for (int r = tid; r < MROWS; r += 1024) {
        float S = g_ps_flat[r];
        int tg = captions[(r & 15) * 257 + (r >> 4) + 1];
        if (tg != 0) local += logf(S) - g_lt[r];
    }
    sh[tid] = local;
    __syncthreads();
    for (int o = 512; o > 0; o >>= 1) {
        if (tid < o) sh[tid] += sh[tid + o];
        __syncthreads();
    }
    if (tid == 0) out[0] = sh[0] * (1.f / NBATCH);
}

// ---------------- launch ----------------
extern "C" void kernel_launch(void* const* d_in, const int* in_sizes, int n_in,
                              void* d_out, int out_size) {
    const int*   captions = (const int*)d_in[0];
    const float* W_embed  = (const float*)d_in[1];
    const float* Wx       = (const float*)d_in[2];
    const float* Wh       = (const float*)d_in[3];
    const float* b        = (const float*)d_in[4];
    const float* W_vocab  = (const float*)d_in[5];
    const float* b_vocab  = (const float*)d_in[6];
    const float* h_init   = (const float*)d_in[7];

    cudaFuncSetAttribute(lstm_kernel,      cudaFuncAttributeMaxDynamicSharedMemorySize, L_SMEM);
    cudaFuncSetAttribute(vocab_kernel,     cudaFuncAttributeMaxDynamicSharedMemorySize, V_SMEM);
    cudaFuncSetAttribute(embed_mma_kernel, cudaFuncAttributeMaxDynamicSharedMemorySize, E_SMEM);

    init_kernel<<<32, 256>>>(h_init, b_vocab);
    prep_kernel<<<768, 256>>>(captions, W_embed, Wx);
    embed_mma_kernel<<<512, 256, E_SMEM>>>(b);
    lstm_kernel<<<LCTAS, 256, L_SMEM>>>(Wh);                   // 4th launch -> profiled
    conv_wv_kernel<<<dim3(VOCABSZ / 32, HIDDEN / 32), 256>>>(W_vocab);
    tgt_kernel<<<512, 256>>>(captions, b_vocab);
    vocab_kernel<<<VCTAS, 256, V_SMEM>>>();
    combine_kernel<<<1, 1024>>>(captions, (float*)d_out);
}